// round 4
// baseline (speedup 1.0000x reference)
#include <cuda_runtime.h>

#define TOKS    2048
#define NNODES  1024
#define FEAT    128
#define QUADS   32                 // FEAT/4 float4 lanes per token row
#define NBLK    64
#define CHUNK   32                 // TOKS / NBLK
#define THREADS 1024
#define NGRP    32                 // warps per block
#define NPW     (NNODES / NGRP)    // 32 nodes per warp

__device__ __forceinline__ float4 f4add(float4 a, float4 b) {
    return make_float4(a.x + b.x, a.y + b.y, a.z + b.z, a.w + b.w);
}

__global__ __launch_bounds__(THREADS, 1)
void span_encoder_kernel(const int* __restrict__ starts,
                         const int* __restrict__ ends,
                         const float4* __restrict__ embed4,
                         float4* __restrict__ out4)
{
    __shared__ __align__(16) int2  s_span[NNODES];       //  8 KB
    __shared__ __align__(16) float sdiff[CHUNK][FEAT];   // 16 KB diff array
    __shared__ __align__(16) float gaccs[NGRP][FEAT];    // 16 KB per-warp acc
    __shared__ __align__(16) float sfull[FEAT];          // combined full sum

    const int tid  = threadIdx.x;
    const int lane = tid & 31;
    const int g    = tid >> 5;               // warp 0..31
    const int q    = lane;                   // float4 lane in feature row
    const int c0   = blockIdx.x * CHUNK;
    const float4 zero4 = make_float4(0.f, 0.f, 0.f, 0.f);

    // ---- Prefetch spans + zero diff array (one parallel pass) -----------
    s_span[tid] = make_int2(__ldg(&starts[tid]), __ldg(&ends[tid]));
    {
        float* df = &sdiff[0][0];
        #pragma unroll
        for (int i = 0; i < (CHUNK * FEAT) / THREADS; ++i)   // 4
            df[i * THREADS + tid] = 0.f;
    }
    __syncthreads();

    // ---- Single pass: classify + accumulate, 32 nodes per warp ----------
    float4 a0 = zero4, a1 = zero4, a2 = zero4, a3 = zero4;
    {
        const int nbase = g * NPW;
        #pragma unroll
        for (int it = 0; it < NPW; it += 4) {
            #pragma unroll
            for (int k = 0; k < 4; ++k) {
                int n   = nbase + it + k;
                int2 se = s_span[n];                    // broadcast LDS.64
                int lo  = se.x - c0;     if (lo < 0)     lo = 0;
                int hi  = se.y - c0 + 1; if (hi > CHUNK) hi = CHUNK;
                if (lo < hi) {
                    if (lo == 0 && hi == CHUNK) {
                        float4 v = __ldg(&embed4[n * QUADS + q]);
                        if      (k == 0) a0 = f4add(a0, v);
                        else if (k == 1) a1 = f4add(a1, v);
                        else if (k == 2) a2 = f4add(a2, v);
                        else             a3 = f4add(a3, v);
                    } else {
                        float4 v = __ldg(&embed4[n * QUADS + q]);
                        float* d = &sdiff[lo][q * 4];
                        atomicAdd(d + 0, v.x);
                        atomicAdd(d + 1, v.y);
                        atomicAdd(d + 2, v.z);
                        atomicAdd(d + 3, v.w);
                        if (hi < CHUNK) {
                            float* d2 = &sdiff[hi][q * 4];
                            atomicAdd(d2 + 0, -v.x);
                            atomicAdd(d2 + 1, -v.y);
                            atomicAdd(d2 + 2, -v.z);
                            atomicAdd(d2 + 3, -v.w);
                        }
                    }
                }
            }
        }
        float4 a = f4add(f4add(a0, a1), f4add(a2, a3));
        ((float4*)gaccs[g])[q] = a;
    }
    __syncthreads();

    // ---- Combine per-warp accumulators (128 threads, one float each) ----
    if (tid < FEAT) {
        float s = gaccs[0][tid];
        #pragma unroll
        for (int gg = 1; gg < NGRP; ++gg) s += gaccs[gg][tid];
        sfull[tid] = s;
    }
    __syncthreads();

    // ---- Scan: warp g owns token c0+g --------------------------------
    {
        float4 acc = ((const float4*)sfull)[q];
        #pragma unroll
        for (int sp = 0; sp < CHUNK - 1; ++sp)
            if (sp < g) acc = f4add(acc, ((const float4*)sdiff[sp])[q]);
        acc = f4add(acc, ((const float4*)sdiff[g])[q]);
        out4[(c0 + g) * QUADS + q] = acc;
    }
}

extern "C" void kernel_launch(void* const* d_in, const int* in_sizes, int n_in,
                              void* d_out, int out_size) {
    const int*    starts = (const int*)d_in[0];
    const int*    ends   = (const int*)d_in[1];
    const float4* embed  = (const float4*)d_in[2];
    float4*       out    = (float4*)d_out;
    (void)in_sizes; (void)n_in; (void)out_size;
    span_encoder_kernel<<<NBLK, THREADS>>>(starts, ends, embed, out);
}